// round 3
// baseline (speedup 1.0000x reference)
#include <cuda_runtime.h>
#include <math.h>

#define BATCH  4
#define SEQ    4096
#define DMODEL 1024
#define DHEAD  64

// Scratch for projected Q/K/V (device globals: allocation rules forbid cudaMalloc)
__device__ float g_Q[BATCH * SEQ * DHEAD];
__device__ float g_K[BATCH * SEQ * DHEAD];
__device__ float g_V[BATCH * SEQ * DHEAD];

// ---------------------------------------------------------------------------
// QKV projection: out[m][n] = sum_k x[m][k] * W[k][n] + b[n]
// grid: (M/64, 3)  block: 128 threads, 4x8 per-thread microtile
// ---------------------------------------------------------------------------
__global__ __launch_bounds__(128) void qkv_proj_kernel(
    const float* __restrict__ x,
    const float* __restrict__ Wq, const float* __restrict__ bq,
    const float* __restrict__ Wk, const float* __restrict__ bk,
    const float* __restrict__ Wv, const float* __restrict__ bv)
{
    const float* W; const float* bias; float* outp;
    if (blockIdx.y == 0)      { W = Wq; bias = bq; outp = g_Q; }
    else if (blockIdx.y == 1) { W = Wk; bias = bk; outp = g_K; }
    else                      { W = Wv; bias = bv; outp = g_V; }

    __shared__ float xs[64 * 36];   // 64 rows x 32 k (pad to 36)
    __shared__ float ws[32 * 68];   // 32 k x 64 n (pad to 68)

    const int tid = threadIdx.x;
    const int ty  = tid >> 3;       // 0..15 -> 4 rows each
    const int tx  = tid & 7;        // 0..7  -> 8 cols each
    const int m0  = blockIdx.x * 64;

    float acc[4][8];
#pragma unroll
    for (int i = 0; i < 4; i++)
#pragma unroll
        for (int j = 0; j < 8; j++) acc[i][j] = 0.f;

    for (int k0 = 0; k0 < DMODEL; k0 += 32) {
        // x tile: 64x32 = 512 float4
#pragma unroll
        for (int l = 0; l < 4; l++) {
            int idx = tid + l * 128;          // 0..511
            int r = idx >> 3;                 // /8 float4 per row
            int c = (idx & 7) << 2;
            float4 v = *(const float4*)(x + (size_t)(m0 + r) * DMODEL + k0 + c);
            *(float4*)(&xs[r * 36 + c]) = v;
        }
        // W tile: 32x64 = 512 float4
#pragma unroll
        for (int l = 0; l < 4; l++) {
            int idx = tid + l * 128;
            int r = idx >> 4;                 // 16 float4 per row
            int c = (idx & 15) << 2;
            float4 v = *(const float4*)(W + (size_t)(k0 + r) * DHEAD + c);
            *(float4*)(&ws[r * 68 + c]) = v;
        }
        __syncthreads();

#pragma unroll
        for (int kk = 0; kk < 32; kk++) {
            float a[4];
#pragma unroll
            for (int i = 0; i < 4; i++) a[i] = xs[(ty * 4 + i) * 36 + kk];
            float4 b0 = *(float4*)(&ws[kk * 68 + tx * 8]);
            float4 b1 = *(float4*)(&ws[kk * 68 + tx * 8 + 4]);
#pragma unroll
            for (int i = 0; i < 4; i++) {
                acc[i][0] += a[i] * b0.x; acc[i][1] += a[i] * b0.y;
                acc[i][2] += a[i] * b0.z; acc[i][3] += a[i] * b0.w;
                acc[i][4] += a[i] * b1.x; acc[i][5] += a[i] * b1.y;
                acc[i][6] += a[i] * b1.z; acc[i][7] += a[i] * b1.w;
            }
        }
        __syncthreads();
    }

#pragma unroll
    for (int i = 0; i < 4; i++) {
        int m = m0 + ty * 4 + i;
#pragma unroll
        for (int j = 0; j < 8; j++) {
            int n = tx * 8 + j;
            outp[(size_t)m * DHEAD + n] = acc[i][j] + bias[n];
        }
    }
}

// ---------------------------------------------------------------------------
// Flash attention, fp32, BM=BN=64, online softmax.
// grid: (32, BATCH); each block processes q-tiles (63-bx) and (bx)
//   -> every block does exactly 65 K-tile iterations (balanced causal work).
// block: 128 threads (ty 0..15 x tx 0..7), 4x8 microtile.
// ---------------------------------------------------------------------------
__global__ __launch_bounds__(128) void attn_kernel(float* __restrict__ outp)
{
    extern __shared__ float smem[];
    float* Qs = smem;                 // [64][68]  Q[m][d]
    float* Kt = Qs + 64 * 68;         // [64][68]  K transposed: Kt[d][n]
    float* Vs = Kt + 64 * 68;         // [64][68]  V[n][h]
    float* Ps = Vs + 64 * 68;         // [64][68]  P[m][n]

    const int b   = blockIdx.y;
    const int tid = threadIdx.x;
    const int ty  = tid >> 3;
    const int tx  = tid & 7;
    const float scale = 0.125f;       // 1/sqrt(64)

    for (int half = 0; half < 2; half++) {
        const int qb = (half == 0) ? (63 - (int)blockIdx.x) : (int)blockIdx.x;

        __syncthreads();  // protect Qs reuse across halves

        // load Q tile: 64x64 = 1024 float4
        const float* Qg = g_Q + ((size_t)b * SEQ + qb * 64) * DHEAD;
#pragma unroll
        for (int l = 0; l < 8; l++) {
            int idx = tid + l * 128;
            int r = idx >> 4, c = (idx & 15) << 2;
            *(float4*)(&Qs[r * 68 + c]) = *(const float4*)(Qg + r * 64 + c);
        }

        float o[4][8];
        float m_i[4], l_i[4];
#pragma unroll
        for (int i = 0; i < 4; i++) {
            m_i[i] = -INFINITY; l_i[i] = 0.f;
#pragma unroll
            for (int j = 0; j < 8; j++) o[i][j] = 0.f;
        }

        for (int kb = 0; kb <= qb; kb++) {
            const float* Kg = g_K + ((size_t)b * SEQ + kb * 64) * DHEAD;
            const float* Vg = g_V + ((size_t)b * SEQ + kb * 64) * DHEAD;
#pragma unroll
            for (int l = 0; l < 8; l++) {
                int idx = tid + l * 128;
                int n = idx >> 4, c = (idx & 15) << 2;
                float4 kv = *(const float4*)(Kg + n * 64 + c);
                Kt[(c + 0) * 68 + n] = kv.x;
                Kt[(c + 1) * 68 + n] = kv.y;
                Kt[(c + 2) * 68 + n] = kv.z;
                Kt[(c + 3) * 68 + n] = kv.w;
                *(float4*)(&Vs[n * 68 + c]) = *(const float4*)(Vg + n * 64 + c);
            }
            __syncthreads();

            // S = Q K^T
            float s[4][8];
#pragma unroll
            for (int i = 0; i < 4; i++)
#pragma unroll
                for (int j = 0; j < 8; j++) s[i][j] = 0.f;

#pragma unroll 8
            for (int d = 0; d < 64; d++) {
                float a[4];
#pragma unroll
                for (int i = 0; i < 4; i++) a[i] = Qs[(ty * 4 + i) * 68 + d];
                float4 k0 = *(float4*)(&Kt[d * 68 + tx * 8]);
                float4 k1 = *(float4*)(&Kt[d * 68 + tx * 8 + 4]);
#pragma unroll
                for (int i = 0; i < 4; i++) {
                    s[i][0] += a[i] * k0.x; s[i][1] += a[i] * k0.y;
                    s[i][2] += a[i] * k0.z; s[i][3] += a[i] * k0.w;
                    s[i][4] += a[i] * k1.x; s[i][5] += a[i] * k1.y;
                    s[i][6] += a[i] * k1.z; s[i][7] += a[i] * k1.w;
                }
            }

            // scale + causal mask on diagonal tile
            const bool diag = (kb == qb);
#pragma unroll
            for (int i = 0; i < 4; i++)
#pragma unroll
                for (int j = 0; j < 8; j++) {
                    s[i][j] *= scale;
                    if (diag && (ty * 4 + i) < (tx * 8 + j)) s[i][j] = -INFINITY;
                }

            // online softmax (rows distributed over the 8 tx lanes of each ty group)
#pragma unroll
            for (int i = 0; i < 4; i++) {
                float mx = s[i][0];
#pragma unroll
                for (int j = 1; j < 8; j++) mx = fmaxf(mx, s[i][j]);
#pragma unroll
                for (int off = 1; off < 8; off <<= 1)
                    mx = fmaxf(mx, __shfl_xor_sync(0xffffffffu, mx, off));
                float m_new = fmaxf(m_i[i], mx);
                float alpha = expf(m_i[i] - m_new);   // first iter: exp(-inf)=0
                float sum = 0.f;
#pragma unroll
                for (int j = 0; j < 8; j++) {
                    float p = expf(s[i][j] - m_new);  // masked: exp(-inf)=0
                    s[i][j] = p;
                    sum += p;
                }
#pragma unroll
                for (int off = 1; off < 8; off <<= 1)
                    sum += __shfl_xor_sync(0xffffffffu, sum, off);
                l_i[i] = l_i[i] * alpha + sum;
                m_i[i] = m_new;
#pragma unroll
                for (int j = 0; j < 8; j++) o[i][j] *= alpha;
#pragma unroll
                for (int j = 0; j < 8; j++)
                    Ps[(ty * 4 + i) * 68 + tx * 8 + j] = s[i][j];
            }
            __syncthreads();

            // O += P V
#pragma unroll 8
            for (int n = 0; n < 64; n++) {
                float p[4];
#pragma unroll
                for (int i = 0; i < 4; i++) p[i] = Ps[(ty * 4 + i) * 68 + n];
                float4 v0 = *(float4*)(&Vs[n * 68 + tx * 8]);
                float4 v1 = *(float4*)(&Vs[n * 68 + tx * 8 + 4]);
#pragma unroll
                for (int i = 0; i < 4; i++) {
                    o[i][0] += p[i] * v0.x; o[i][1] += p[i] * v0.y;
                    o[i][2] += p[i] * v0.z; o[i][3] += p[i] * v0.w;
                    o[i][4] += p[i] * v1.x; o[i][5] += p[i] * v1.y;
                    o[i][6] += p[i] * v1.z; o[i][7] += p[i] * v1.w;
                }
            }
            __syncthreads();
        }

        // normalize and write
#pragma unroll
        for (int i = 0; i < 4; i++) {
            float inv = 1.f / l_i[i];
            int m = qb * 64 + ty * 4 + i;
            float* og = outp + ((size_t)b * SEQ + m) * DHEAD + tx * 8;
#pragma unroll
            for (int j = 0; j < 8; j++) og[j] = o[i][j] * inv;
        }
    }
}

// ---------------------------------------------------------------------------
extern "C" void kernel_launch(void* const* d_in, const int* in_sizes, int n_in,
                              void* d_out, int out_size)
{
    const float* x  = (const float*)d_in[0];
    const float* Wq = (const float*)d_in[1];
    const float* bq = (const float*)d_in[2];
    const float* Wk = (const float*)d_in[3];
    const float* bk = (const float*)d_in[4];
    const float* Wv = (const float*)d_in[5];
    const float* bv = (const float*)d_in[6];
    float* outp = (float*)d_out;

    qkv_proj_kernel<<<dim3((BATCH * SEQ) / 64, 3), 128>>>(x, Wq, bq, Wk, bk, Wv, bv);

    const int smem_bytes = 4 * 64 * 68 * (int)sizeof(float);  // 69632
    cudaFuncSetAttribute(attn_kernel, cudaFuncAttributeMaxDynamicSharedMemorySize,
                         smem_bytes);
    attn_kernel<<<dim3(32, BATCH), 128, smem_bytes>>>(outp);
}